// round 3
// baseline (speedup 1.0000x reference)
#include <cuda_runtime.h>
#include <math.h>

#define T_STEPS 1000
#define NS 10
#define NTRAJ 256
#define CHUNKS 100
#define CLEN 10

#define TRAJ_STRIDE (NS*(T_STEPS+1))            /* 10010 floats per trajectory */
#define OUT_TRAJ_SIZE (NTRAJ*TRAJ_STRIDE)       /* 2,562,560 */
#define OUT_PK_OFF   OUT_TRAJ_SIZE
#define OUT_PK_SIZE  (NTRAJ*(T_STEPS+1)*NS*NS)  /* 25,625,600 */
#define OUT_MSE_OFF  (OUT_PK_OFF+OUT_PK_SIZE)   /* 28,188,160 */

// -------- scratch (no allocations allowed) --------
__device__ __align__(16) float d_Amat[T_STEPS*100];  // A_t = (I - K_t H) F
__device__ __align__(16) float d_Kmat[T_STEPS*100];  // K_t
__device__ __align__(16) float d_Pp  [T_STEPS*100];  // P_pos_t
__device__ __align__(16) float d_Mc  [CHUNKS*100];   // chunk products
__device__ __align__(16) float d_Vc  [NTRAJ*CHUNKS*NS]; // chunk-local affine constants
__device__ __align__(16) float d_Xst [NTRAJ*CHUNKS*NS]; // state at chunk starts
__device__ float d_partial[NTRAJ*CHUNKS];            // per (traj,chunk) squared-error sums

// ============================================================================
// Kernel 1: serial Riccati recursion (single block). Standard covariance form
// (mathematically identical to the reference's square-root form).
//   P_neg = F P F^T + Q ; S = H P_neg H^T + R ; K = P_neg H^T S^-1
//   P_pos = P_neg - K (P_neg H^T)^T  (then symmetrized)
//   A_t = F - K (H F)
// Converges geometrically; fill-forward after max|dP| < 1e-6.
// ============================================================================
__global__ void riccati_kernel(const float* __restrict__ Fg,
                               const float* __restrict__ Hg,
                               const float* __restrict__ Qg,
                               const float* __restrict__ Rg)
{
    __shared__ float Fs[100], Hs[100], HFs[100], Qs[100], Rs[100];
    __shared__ float P[100], FP[100], Pn[100], W[100], Sb[2][100], Ks[100];
    __shared__ int notconv;

    const int tid = threadIdx.x;
    const int r = tid / 10, c = tid % 10;
    const bool act = tid < 100;

    if (act) { Fs[tid] = Fg[tid]; Hs[tid] = Hg[tid]; Qs[tid] = Qg[tid]; Rs[tid] = Rg[tid]; }
    __syncthreads();
    if (act) {
        float s = 0.f;
        #pragma unroll
        for (int j = 0; j < 10; ++j) s += Hs[r*10+j] * Fs[j*10+c];
        HFs[tid] = s;
        P[tid] = (r == c) ? 1.f : 0.f;
    }
    __syncthreads();

    for (int t = 0; t < T_STEPS; ++t) {
        // FP = F * P
        if (act) {
            float s = 0.f;
            #pragma unroll
            for (int j = 0; j < 10; ++j) s += Fs[r*10+j] * P[j*10+c];
            FP[tid] = s;
        }
        __syncthreads();
        // Pn = FP * F^T + Q
        if (act) {
            float s = Qs[tid];
            #pragma unroll
            for (int j = 0; j < 10; ++j) s += FP[r*10+j] * Fs[c*10+j];
            Pn[tid] = s;
        }
        __syncthreads();
        // W = Pn * H^T
        if (act) {
            float s = 0.f;
            #pragma unroll
            for (int j = 0; j < 10; ++j) s += Pn[r*10+j] * Hs[c*10+j];
            W[tid] = s;
        }
        __syncthreads();
        // S = H * W + R
        if (act) {
            float s = Rs[tid];
            #pragma unroll
            for (int j = 0; j < 10; ++j) s += Hs[r*10+j] * W[j*10+c];
            Sb[0][tid] = s;
        }
        __syncthreads();
        // Gauss-Jordan inverse of S (SPD, diagonally strong -> no pivoting)
        #pragma unroll 1
        for (int k = 0; k < 10; ++k) {
            const float* src = Sb[k & 1];
            float*       dst = Sb[(k + 1) & 1];
            if (act) {
                float p = 1.0f / src[k*10+k];
                float v;
                if (r == k && c == k)      v = p;
                else if (r == k)           v = src[k*10+c] * p;
                else if (c == k)           v = -src[r*10+k] * p;
                else                       v = src[r*10+c] - src[r*10+k] * src[k*10+c] * p;
                dst[tid] = v;
            }
            __syncthreads();
        }
        const float* Sinv = Sb[0];  // 10 swaps -> back to buffer 0
        // K = W * Sinv
        if (act) {
            float s = 0.f;
            #pragma unroll
            for (int j = 0; j < 10; ++j) s += W[r*10+j] * Sinv[j*10+c];
            Ks[tid] = s;
        }
        __syncthreads();
        // Pnew(unsym) = Pn - K * W^T   (into FP as temp)
        if (act) {
            float s = 0.f;
            #pragma unroll
            for (int j = 0; j < 10; ++j) s += Ks[r*10+j] * W[c*10+j];
            FP[tid] = Pn[tid] - s;
        }
        if (tid == 0) notconv = 0;
        __syncthreads();

        float pnew = 0.f, kval = 0.f, aval = 0.f;
        if (act) {
            pnew = 0.5f * (FP[r*10+c] + FP[c*10+r]);  // symmetrize
            float d = fabsf(pnew - P[tid]);
            if (d > 1e-6f) notconv = 1;
            P[tid] = pnew;
            kval = Ks[tid];
            float s = 0.f;
            #pragma unroll
            for (int j = 0; j < 10; ++j) s += kval * 0.f, s += Ks[r*10+j] * HFs[j*10+c];
            aval = Fs[tid] - s;
            d_Pp  [t*100 + tid] = pnew;
            d_Kmat[t*100 + tid] = kval;
            d_Amat[t*100 + tid] = aval;
        }
        __syncthreads();

        if (!notconv) {
            // converged: fill-forward remaining steps with steady-state values
            if (act) {
                for (int tt = t + 1; tt < T_STEPS; ++tt) {
                    d_Pp  [tt*100 + tid] = pnew;
                    d_Kmat[tt*100 + tid] = kval;
                    d_Amat[tt*100 + tid] = aval;
                }
            }
            break;
        }
    }
}

// ============================================================================
// Kernel 2: chunk matrix products  M_c = A_{c*L+L-1} * ... * A_{c*L}
// ============================================================================
__global__ void chunkmat_kernel()
{
    __shared__ float M[2][100];
    const int chunk = blockIdx.x;
    const int tid = threadIdx.x;
    const int r = tid / 10, c = tid % 10;
    const bool act = tid < 100;

    if (act) M[0][tid] = d_Amat[(chunk*CLEN)*100 + tid];
    __syncthreads();
    for (int l = 1; l < CLEN; ++l) {
        const float* An = &d_Amat[(chunk*CLEN + l)*100];
        if (act) {
            float s = 0.f;
            #pragma unroll
            for (int j = 0; j < 10; ++j) s += An[r*10+j] * M[(l-1)&1][j*10+c];
            M[l & 1][tid] = s;
        }
        __syncthreads();
    }
    if (act) d_Mc[chunk*100 + tid] = M[(CLEN-1) & 1][tid];
}

// ============================================================================
// Kernel 3: chunk-local affine constants  v_c(traj) = scan with x_start = 0
//   grid = CHUNKS blocks, blockDim = NTRAJ threads (thread == trajectory)
// ============================================================================
__global__ void chunkv_kernel(const float* __restrict__ Y)
{
    __shared__ float Ash[CLEN][100];
    __shared__ float Ksh[CLEN][100];
    const int chunk = blockIdx.x;
    const int traj  = threadIdx.x;

    for (int i = threadIdx.x; i < CLEN*100; i += blockDim.x) {
        Ash[i/100][i%100] = d_Amat[chunk*CLEN*100 + i];
        Ksh[i/100][i%100] = d_Kmat[chunk*CLEN*100 + i];
    }
    __syncthreads();

    float v[10];
    #pragma unroll
    for (int i = 0; i < 10; ++i) v[i] = 0.f;

    const float* yb = Y + (size_t)traj * (T_STEPS*NS) + chunk*CLEN*NS;
    for (int l = 0; l < CLEN; ++l) {
        float y[10];
        #pragma unroll
        for (int j = 0; j < 10; ++j) y[j] = yb[l*10 + j];
        float nv[10];
        #pragma unroll
        for (int i = 0; i < 10; ++i) {
            float s = 0.f;
            #pragma unroll
            for (int j = 0; j < 10; ++j) s += Ksh[l][i*10+j] * y[j];
            #pragma unroll
            for (int j = 0; j < 10; ++j) s += Ash[l][i*10+j] * v[j];
            nv[i] = s;
        }
        #pragma unroll
        for (int i = 0; i < 10; ++i) v[i] = nv[i];
    }
    #pragma unroll
    for (int i = 0; i < 10; ++i)
        d_Vc[((size_t)traj*CHUNKS + chunk)*NS + i] = v[i];
}

// ============================================================================
// Kernel 4: serial chain over chunks: X_c = M_c X_{c-1} + V_c ; records X at
// chunk starts.  grid = 8 blocks, blockDim = 320 (32 traj x 10 rows)
// ============================================================================
__global__ void chainscan_kernel()
{
    __shared__ float xs[32][10];
    __shared__ float Ms[100];
    const int g = threadIdx.x / 10;
    const int i = threadIdx.x % 10;
    const int traj = blockIdx.x * 32 + g;

    xs[g][i] = 0.f;
    __syncthreads();
    for (int ch = 0; ch < CHUNKS; ++ch) {
        d_Xst[((size_t)traj*CHUNKS + ch)*NS + i] = xs[g][i];
        if (threadIdx.x < 100) Ms[threadIdx.x] = d_Mc[ch*100 + threadIdx.x];
        float v = d_Vc[((size_t)traj*CHUNKS + ch)*NS + i];
        __syncthreads();
        float s = v;
        #pragma unroll
        for (int j = 0; j < 10; ++j) s += Ms[i*10+j] * xs[g][j];
        __syncthreads();
        xs[g][i] = s;
        __syncthreads();
    }
}

// ============================================================================
// Kernel 5: replay each chunk from its recorded start state; write traj output
// and accumulate per-(traj,chunk) squared error.  grid=CHUNKS, blockDim=NTRAJ
// ============================================================================
__global__ void replay_kernel(const float* __restrict__ Y,
                              const float* __restrict__ X,
                              float* __restrict__ out, int out_size)
{
    __shared__ float Ash[CLEN][100];
    __shared__ float Ksh[CLEN][100];
    const int chunk = blockIdx.x;
    const int traj  = threadIdx.x;

    for (int i = threadIdx.x; i < CLEN*100; i += blockDim.x) {
        Ash[i/100][i%100] = d_Amat[chunk*CLEN*100 + i];
        Ksh[i/100][i%100] = d_Kmat[chunk*CLEN*100 + i];
    }
    __syncthreads();

    float x[10];
    #pragma unroll
    for (int i = 0; i < 10; ++i)
        x[i] = d_Xst[((size_t)traj*CHUNKS + chunk)*NS + i];

    const bool wr = (out_size >= OUT_TRAJ_SIZE);
    float errsum = 0.f;
    const float* yb = Y + (size_t)traj * (T_STEPS*NS);
    const float* xb = X + (size_t)traj * TRAJ_STRIDE;
    float* ob = out + (size_t)traj * TRAJ_STRIDE;

    for (int l = 0; l < CLEN; ++l) {
        const int t = chunk*CLEN + l;
        float y[10];
        #pragma unroll
        for (int j = 0; j < 10; ++j) y[j] = yb[t*10 + j];
        float nx[10];
        #pragma unroll
        for (int i = 0; i < 10; ++i) {
            float s = 0.f;
            #pragma unroll
            for (int j = 0; j < 10; ++j) s += Ksh[l][i*10+j] * y[j];
            #pragma unroll
            for (int j = 0; j < 10; ++j) s += Ash[l][i*10+j] * x[j];
            nx[i] = s;
        }
        #pragma unroll
        for (int i = 0; i < 10; ++i) x[i] = nx[i];
        #pragma unroll
        for (int i = 0; i < 10; ++i) {
            if (wr) ob[(t+1)*10 + i] = x[i];
            float d = xb[(t+1)*10 + i] - x[i];
            errsum += d * d;
        }
    }
    d_partial[traj*CHUNKS + chunk] = errsum;
}

// ============================================================================
// Kernel 6: MSE reduction -> scalar (dB averaged over trajectories)
// ============================================================================
__global__ void mse_kernel(float* __restrict__ out, int out_size)
{
    __shared__ float red[NTRAJ];
    const int traj = threadIdx.x;
    float s = 0.f;
    for (int ch = 0; ch < CHUNKS; ++ch) s += d_partial[traj*CHUNKS + ch];
    float mse = s / (float)(T_STEPS * NS);
    red[traj] = 10.f * log10f(mse);
    __syncthreads();
    for (int off = NTRAJ/2; off > 0; off >>= 1) {
        if (traj < off) red[traj] += red[traj + off];
        __syncthreads();
    }
    if (traj == 0 && OUT_MSE_OFF < out_size)
        out[OUT_MSE_OFF] = red[0] / (float)NTRAJ;
}

// ============================================================================
// Kernel 7: broadcast Pk (t==0 -> zeros), zero traj[:,0,:]. Memory-bound.
// ============================================================================
__global__ void pk_kernel(float* __restrict__ out, int out_size)
{
    // traj t=0 zeros
    int tg = blockIdx.x * blockDim.x + threadIdx.x;
    if (tg < NTRAJ*NS && out_size >= OUT_TRAJ_SIZE) {
        int traj = tg / NS, i = tg % NS;
        out[(size_t)traj*TRAJ_STRIDE + i] = 0.f;
    }
    if (out_size < OUT_PK_OFF + 4) return;
    long total4 = (long)OUT_PK_SIZE / 4;                 // 6,406,400 float4s
    long lim4 = ((long)out_size - OUT_PK_OFF) / 4;
    if (lim4 < total4) total4 = lim4;
    float4* outp = (float4*)(out + OUT_PK_OFF);
    const long stride = (long)gridDim.x * blockDim.x;
    for (long idx = tg; idx < total4; idx += stride) {
        int e4 = (int)(idx % 25);
        long rem = idx / 25;
        int t = (int)(rem % (T_STEPS + 1));
        float4 v;
        if (t == 0) v = make_float4(0.f, 0.f, 0.f, 0.f);
        else        v = *(const float4*)&d_Pp[(t-1)*100 + e4*4];
        outp[idx] = v;
    }
}

// ============================================================================
extern "C" void kernel_launch(void* const* d_in, const int* in_sizes, int n_in,
                              void* d_out, int out_size)
{
    const float* X = (const float*)d_in[0];
    const float* Y = (const float*)d_in[1];
    const float* F = (const float*)d_in[2];
    const float* H = (const float*)d_in[3];
    const float* Q = (const float*)d_in[4];
    const float* R = (const float*)d_in[5];
    float* out = (float*)d_out;

    riccati_kernel <<<1, 128>>>(F, H, Q, R);
    chunkmat_kernel<<<CHUNKS, 128>>>();
    chunkv_kernel  <<<CHUNKS, NTRAJ>>>(Y);
    chainscan_kernel<<<8, 320>>>();
    replay_kernel  <<<CHUNKS, NTRAJ>>>(Y, X, out, out_size);
    mse_kernel     <<<1, NTRAJ>>>(out, out_size);
    pk_kernel      <<<2048, 256>>>(out, out_size);
}

// round 5
// speedup vs baseline: 1.5215x; 1.5215x over previous
#include <cuda_runtime.h>
#include <math.h>

#define T_STEPS 1000
#define NS 10
#define NTRAJ 256
#define CHUNKS 100
#define CLEN 10

#define TRAJ_STRIDE (NS*(T_STEPS+1))            /* 10010 floats per trajectory */
#define OUT_TRAJ_SIZE (NTRAJ*TRAJ_STRIDE)       /* 2,562,560 */
#define OUT_PK_OFF   OUT_TRAJ_SIZE
#define OUT_PK_SIZE  (NTRAJ*(T_STEPS+1)*NS*NS)  /* 25,625,600 */
#define OUT_MSE_OFF  (OUT_PK_OFF+OUT_PK_SIZE)   /* 28,188,160 */

// -------- scratch (no allocations allowed) --------
__device__ __align__(16) float d_Amat[T_STEPS*100];   // A_t = (I - K_t H) F  (only [0..tconv] valid)
__device__ __align__(16) float d_Kmat[T_STEPS*100];   // K_t                  (only [0..tconv] valid)
__device__ __align__(16) float d_Pp  [T_STEPS*100];   // P_pos_t              (only [0..tconv] valid)
__device__ int d_tconv;                               // last computed step; clamp reads to this
__device__ __align__(16) float d_Mc  [CHUNKS*100];    // chunk products
__device__ __align__(16) float d_Vc  [CHUNKS*NTRAJ*NS]; // chunk-local affine constants [chunk][traj][i]
__device__ __align__(16) float d_Xst [CHUNKS*NTRAJ*NS]; // state at chunk starts        [chunk][traj][i]
__device__ float d_partial[CHUNKS*NTRAJ];             // per (chunk,traj) squared-error sums

// ============================================================================
// Kernel 1: serial Riccati recursion (single block, 128 threads).
//   P_neg = F P F^T + Q ; S = H P_neg H^T + R ; K = P_neg H^T S^-1
//   P_pos = P_neg - sym(K W^T) ; A = F - K (H F)
// Gauss-Jordan inverse of S done inside warp 0 with shuffles (1 barrier).
// Stops at convergence (max|dP| < 1e-6); consumers clamp t to d_tconv.
// ============================================================================
__global__ void riccati_kernel(const float* __restrict__ Fg,
                               const float* __restrict__ Hg,
                               const float* __restrict__ Qg,
                               const float* __restrict__ Rg)
{
    __shared__ float Fs[100], Hs[100], HFs[100];
    __shared__ float P[100], FP[100], Pn[100], W[100], Ssh[100], Sinv[100], Ks[100];

    const int tid = threadIdx.x;
    const int r = tid / 10, c = tid % 10;
    const bool act = tid < 100;

    if (act) { Fs[tid] = Fg[tid]; Hs[tid] = Hg[tid]; }
    __syncthreads();

    float Frow[10], FrowC[10], HrowR[10], HrowC[10], HFcol[10];
    float qv = 0.f, rv = 0.f;
    if (act) {
        qv = Qg[tid]; rv = Rg[tid];
        #pragma unroll
        for (int j = 0; j < 10; ++j) {
            Frow[j]  = Fs[r*10+j];
            FrowC[j] = Fs[c*10+j];
            HrowR[j] = Hs[r*10+j];
            HrowC[j] = Hs[c*10+j];
        }
        float s = 0.f;
        #pragma unroll
        for (int j = 0; j < 10; ++j) s += HrowR[j] * Fs[j*10+c];
        HFs[tid] = s;
        P[tid] = (r == c) ? 1.f : 0.f;
    }
    __syncthreads();
    if (act) {
        #pragma unroll
        for (int j = 0; j < 10; ++j) HFcol[j] = HFs[j*10+c];
    }

    int tconv = T_STEPS - 1;
    for (int t = 0; t < T_STEPS; ++t) {
        // FP = F * P
        if (act) {
            float s = 0.f;
            #pragma unroll
            for (int j = 0; j < 10; ++j) s += Frow[j] * P[j*10+c];
            FP[tid] = s;
        }
        __syncthreads();
        // Pn = FP * F^T + Q
        if (act) {
            float s = qv;
            #pragma unroll
            for (int j = 0; j < 10; ++j) s += FP[r*10+j] * FrowC[j];
            Pn[tid] = s;
        }
        __syncthreads();
        // W = Pn * H^T
        if (act) {
            float s = 0.f;
            #pragma unroll
            for (int j = 0; j < 10; ++j) s += Pn[r*10+j] * HrowC[j];
            W[tid] = s;
        }
        __syncthreads();
        // S = H * W + R
        if (act) {
            float s = rv;
            #pragma unroll
            for (int j = 0; j < 10; ++j) s += HrowR[j] * W[j*10+c];
            Ssh[tid] = s;
        }
        __syncthreads();
        // In-warp Gauss-Jordan inverse of S (warp 0, lanes 0-9 hold rows)
        if (tid < 32) {
            const int lr = (tid < 10) ? tid : 0;
            float sv[10];
            #pragma unroll
            for (int j = 0; j < 10; ++j) sv[j] = Ssh[lr*10+j];
            #pragma unroll
            for (int k = 0; k < 10; ++k) {
                float rk[10];
                #pragma unroll
                for (int j = 0; j < 10; ++j)
                    rk[j] = __shfl_sync(0xffffffffu, sv[j], k);
                float pinv = 1.0f / rk[k];
                if (tid == k) {
                    #pragma unroll
                    for (int j = 0; j < 10; ++j) sv[j] = rk[j] * pinv;
                    sv[k] = pinv;
                } else {
                    float f = sv[k] * pinv;
                    #pragma unroll
                    for (int j = 0; j < 10; ++j)
                        if (j != k) sv[j] -= f * rk[j];
                    sv[k] = -f;
                }
            }
            if (tid < 10) {
                #pragma unroll
                for (int j = 0; j < 10; ++j) Sinv[tid*10+j] = sv[j];
            }
        }
        __syncthreads();
        // K = W * Sinv
        if (act) {
            float s = 0.f;
            #pragma unroll
            for (int j = 0; j < 10; ++j) s += W[r*10+j] * Sinv[j*10+c];
            Ks[tid] = s;
        }
        __syncthreads();
        // Fused: Pnew = Pn - sym(K W^T), A = F - K*HF, store, convergence
        bool pred = false;
        if (act) {
            float s1 = 0.f, s2 = 0.f, sa = 0.f;
            #pragma unroll
            for (int j = 0; j < 10; ++j) {
                s1 += Ks[r*10+j] * W[c*10+j];
                s2 += W[r*10+j] * Ks[c*10+j];
                sa += Ks[r*10+j] * HFcol[j];
            }
            float pnew = Pn[tid] - 0.5f * (s1 + s2);
            float aval = Fs[tid] - sa;
            pred = fabsf(pnew - P[tid]) > 1e-6f;
            d_Pp  [t*100 + tid] = pnew;
            d_Kmat[t*100 + tid] = Ks[tid];
            d_Amat[t*100 + tid] = aval;
            P[tid] = pnew;
        }
        if (!__syncthreads_or(pred)) { tconv = t; break; }
    }
    if (tid == 0) d_tconv = tconv;
}

// ============================================================================
// Kernel 2 (fused): per-chunk A/K tiles -> chunk matrix product M_c AND
// chunk-local affine constants v_c (zero-start scan). grid=CHUNKS, block=256.
// ============================================================================
__global__ void chunkv_kernel(const float* __restrict__ Y)
{
    __shared__ float Ash[CLEN][100];
    __shared__ float Ksh[CLEN][100];
    __shared__ float Mb[2][100];
    const int chunk = blockIdx.x;
    const int tid = threadIdx.x;
    const int tconv = d_tconv;

    for (int i = tid; i < CLEN*100; i += blockDim.x) {
        int l = i / 100, e = i % 100;
        int tc = min(chunk*CLEN + l, tconv);
        Ash[l][e] = d_Amat[tc*100 + e];
        Ksh[l][e] = d_Kmat[tc*100 + e];
    }
    __syncthreads();

    // ---- chunk matrix product (threads 0-99) ----
    const int r = tid / 10, c = tid % 10;
    const bool act = tid < 100;
    if (act) Mb[0][tid] = Ash[0][tid];
    __syncthreads();
    for (int l = 1; l < CLEN; ++l) {
        if (act) {
            float s = 0.f;
            #pragma unroll
            for (int j = 0; j < 10; ++j) s += Ash[l][r*10+j] * Mb[(l-1)&1][j*10+c];
            Mb[l & 1][tid] = s;
        }
        __syncthreads();
    }
    if (act) d_Mc[chunk*100 + tid] = Mb[(CLEN-1) & 1][tid];

    // ---- v-scan: thread == trajectory ----
    const int traj = tid;
    float v[10];
    #pragma unroll
    for (int i = 0; i < 10; ++i) v[i] = 0.f;

    const float* yb = Y + (size_t)traj * (T_STEPS*NS) + chunk*CLEN*NS;
    for (int l = 0; l < CLEN; ++l) {
        float y[10];
        #pragma unroll
        for (int j = 0; j < 10; ++j) y[j] = yb[l*10 + j];
        float nv[10];
        #pragma unroll
        for (int i = 0; i < 10; ++i) {
            float s = 0.f;
            #pragma unroll
            for (int j = 0; j < 10; ++j) s += Ksh[l][i*10+j] * y[j];
            #pragma unroll
            for (int j = 0; j < 10; ++j) s += Ash[l][i*10+j] * v[j];
            nv[i] = s;
        }
        #pragma unroll
        for (int i = 0; i < 10; ++i) v[i] = nv[i];
    }
    #pragma unroll
    for (int i = 0; i < 10; ++i)
        d_Vc[((size_t)chunk*NTRAJ + traj)*NS + i] = v[i];
}

// ============================================================================
// Kernel 3: serial chain over chunks, shuffle-based, no barriers in loop.
// 10 lanes per trajectory (3 traj per warp), all 100 M matrices in smem,
// 4-deep register prefetch pipeline for V. grid=11, block=256 (88 warps).
// ============================================================================
#define CS_STEP(CH, VREG)                                                      \
    do {                                                                       \
        if (valid) d_Xst[((size_t)(CH)*NTRAJ + traj)*NS + row] = x;            \
        float xn = (VREG);                                                     \
        _Pragma("unroll")                                                      \
        for (int j = 0; j < 10; ++j)                                           \
            xn += Ms[(CH)*100 + row*10 + j] *                                  \
                  __shfl_sync(0xffffffffu, x, sub*10 + j);                     \
        x = xn;                                                                \
    } while (0)

__global__ void chainscan_kernel()
{
    __shared__ float Ms[CHUNKS*100];   // 40 KB
    const int tid = threadIdx.x;

    {
        const float4* src = (const float4*)d_Mc;
        float4* dst = (float4*)Ms;
        for (int i = tid; i < CHUNKS*100/4; i += blockDim.x) dst[i] = src[i];
    }
    __syncthreads();

    const int warpId = tid / 32, lane = tid % 32;
    const int sub = lane / 10, row = lane - sub*10;
    const int traj = (blockIdx.x * (blockDim.x/32) + warpId) * 3 + sub;
    const bool valid = (lane < 30) && (traj < NTRAJ);

    float x = 0.f;
    float vb0, vb1, vb2, vb3;
    #define LDV(CH) ((valid && (CH) < CHUNKS) ? d_Vc[((size_t)(CH)*NTRAJ + traj)*NS + row] : 0.f)
    vb0 = LDV(0); vb1 = LDV(1); vb2 = LDV(2); vb3 = LDV(3);

    for (int ch = 0; ch < CHUNKS; ch += 4) {
        CS_STEP(ch + 0, vb0); vb0 = LDV(ch + 4);
        CS_STEP(ch + 1, vb1); vb1 = LDV(ch + 5);
        CS_STEP(ch + 2, vb2); vb2 = LDV(ch + 6);
        CS_STEP(ch + 3, vb3); vb3 = LDV(ch + 7);
    }
    #undef LDV
}

// ============================================================================
// Kernel 4: replay each chunk from its recorded start state; write traj output
// and accumulate per-(chunk,traj) squared error. grid=CHUNKS, block=NTRAJ.
// ============================================================================
__global__ void replay_kernel(const float* __restrict__ Y,
                              const float* __restrict__ X,
                              float* __restrict__ out, int out_size)
{
    __shared__ float Ash[CLEN][100];
    __shared__ float Ksh[CLEN][100];
    const int chunk = blockIdx.x;
    const int traj  = threadIdx.x;
    const int tconv = d_tconv;

    for (int i = threadIdx.x; i < CLEN*100; i += blockDim.x) {
        int l = i / 100, e = i % 100;
        int tc = min(chunk*CLEN + l, tconv);
        Ash[l][e] = d_Amat[tc*100 + e];
        Ksh[l][e] = d_Kmat[tc*100 + e];
    }
    __syncthreads();

    float x[10];
    #pragma unroll
    for (int i = 0; i < 10; ++i)
        x[i] = d_Xst[((size_t)chunk*NTRAJ + traj)*NS + i];

    const bool wr = (out_size >= OUT_TRAJ_SIZE);
    float errsum = 0.f;
    const float* yb = Y + (size_t)traj * (T_STEPS*NS);
    const float* xb = X + (size_t)traj * TRAJ_STRIDE;
    float* ob = out + (size_t)traj * TRAJ_STRIDE;

    for (int l = 0; l < CLEN; ++l) {
        const int t = chunk*CLEN + l;
        float y[10];
        #pragma unroll
        for (int j = 0; j < 10; ++j) y[j] = yb[t*10 + j];
        float nx[10];
        #pragma unroll
        for (int i = 0; i < 10; ++i) {
            float s = 0.f;
            #pragma unroll
            for (int j = 0; j < 10; ++j) s += Ksh[l][i*10+j] * y[j];
            #pragma unroll
            for (int j = 0; j < 10; ++j) s += Ash[l][i*10+j] * x[j];
            nx[i] = s;
        }
        #pragma unroll
        for (int i = 0; i < 10; ++i) x[i] = nx[i];
        #pragma unroll
        for (int i = 0; i < 10; ++i) {
            if (wr) ob[(t+1)*10 + i] = x[i];
            float d = xb[(t+1)*10 + i] - x[i];
            errsum += d * d;
        }
    }
    d_partial[(size_t)chunk*NTRAJ + traj] = errsum;
}

// ============================================================================
// Kernel 5: MSE reduction -> scalar (dB averaged over trajectories)
// ============================================================================
__global__ void mse_kernel(float* __restrict__ out, int out_size)
{
    __shared__ float red[NTRAJ];
    const int traj = threadIdx.x;
    float s = 0.f;
    for (int ch = 0; ch < CHUNKS; ++ch) s += d_partial[(size_t)ch*NTRAJ + traj];
    float mse = s / (float)(T_STEPS * NS);
    red[traj] = 10.f * log10f(mse);
    __syncthreads();
    for (int off = NTRAJ/2; off > 0; off >>= 1) {
        if (traj < off) red[traj] += red[traj + off];
        __syncthreads();
    }
    if (traj == 0 && OUT_MSE_OFF < out_size)
        out[OUT_MSE_OFF] = red[0] / (float)NTRAJ;
}

// ============================================================================
// Kernel 6: broadcast Pk (t==0 -> zeros, t>tconv -> steady row), zero traj t=0.
// Memory-bound (102 MB of stores).
// ============================================================================
__global__ void pk_kernel(float* __restrict__ out, int out_size)
{
    const int tconv = d_tconv;
    int tg = blockIdx.x * blockDim.x + threadIdx.x;
    if (tg < NTRAJ*NS && out_size >= OUT_TRAJ_SIZE) {
        int traj = tg / NS, i = tg % NS;
        out[(size_t)traj*TRAJ_STRIDE + i] = 0.f;
    }
    if (out_size < OUT_PK_OFF + 4) return;
    long total4 = (long)OUT_PK_SIZE / 4;
    long lim4 = ((long)out_size - OUT_PK_OFF) / 4;
    if (lim4 < total4) total4 = lim4;
    float4* outp = (float4*)(out + OUT_PK_OFF);
    const long stride = (long)gridDim.x * blockDim.x;
    for (long idx = tg; idx < total4; idx += stride) {
        int e4 = (int)(idx % 25);
        long rem = idx / 25;
        int t = (int)(rem % (T_STEPS + 1));
        float4 v;
        if (t == 0) v = make_float4(0.f, 0.f, 0.f, 0.f);
        else {
            int tc = min(t - 1, tconv);
            v = *(const float4*)&d_Pp[tc*100 + e4*4];
        }
        outp[idx] = v;
    }
}

// ============================================================================
extern "C" void kernel_launch(void* const* d_in, const int* in_sizes, int n_in,
                              void* d_out, int out_size)
{
    const float* X = (const float*)d_in[0];
    const float* Y = (const float*)d_in[1];
    const float* F = (const float*)d_in[2];
    const float* H = (const float*)d_in[3];
    const float* Q = (const float*)d_in[4];
    const float* R = (const float*)d_in[5];
    float* out = (float*)d_out;

    riccati_kernel  <<<1, 128>>>(F, H, Q, R);
    chunkv_kernel   <<<CHUNKS, NTRAJ>>>(Y);
    chainscan_kernel<<<11, 256>>>();
    replay_kernel   <<<CHUNKS, NTRAJ>>>(Y, X, out, out_size);
    mse_kernel      <<<1, NTRAJ>>>(out, out_size);
    pk_kernel       <<<2048, 256>>>(out, out_size);
}

// round 7
// speedup vs baseline: 1.6494x; 1.0840x over previous
#include <cuda_runtime.h>
#include <math.h>

#define T_STEPS 1000
#define NS 10
#define NTRAJ 256
#define CHUNKS 100
#define CLEN 10

#define TRAJ_STRIDE (NS*(T_STEPS+1))            /* 10010 floats per trajectory */
#define OUT_TRAJ_SIZE (NTRAJ*TRAJ_STRIDE)       /* 2,562,560 */
#define OUT_PK_OFF   OUT_TRAJ_SIZE
#define OUT_PK_SIZE  (NTRAJ*(T_STEPS+1)*NS*NS)  /* 25,625,600 */
#define OUT_MSE_OFF  (OUT_PK_OFF+OUT_PK_SIZE)   /* 28,188,160 */

// fused_mid launch geometry
#define NB_V  1100     /* chunkv role blocks: 100 chunks x 11 slices          */
#define NB_M  100      /* chunkmat role blocks                                */
#define NB_PK 1200     /* pk role blocks                                      */
#define NB_MID 2400    /* even b -> compute(b/2), odd b -> pk(b/2)            */

// -------- scratch (no allocations allowed) --------
__device__ __align__(16) float d_Amat[T_STEPS*100];   // A_t = (I - K_t H) F  (valid to tconv)
__device__ __align__(16) float d_Kmat[T_STEPS*100];   // K_t                  (valid to tconv)
__device__ __align__(16) float d_Pp  [T_STEPS*100];   // P_pos_t              (valid to tconv)
__device__ int d_tconv;
__device__ __align__(16) float d_Mc  [CHUNKS*100];      // chunk products
__device__ __align__(16) float d_Vc  [CHUNKS*NTRAJ*NS]; // chunk-local affine constants
__device__ __align__(16) float d_Xst [CHUNKS*NTRAJ*NS]; // state at chunk starts
__device__ float d_partial[CHUNKS*NTRAJ];               // per (chunk,traj) sq-error sums

// ============================================================================
// Kernel 1: serial Riccati recursion (single block, 128 threads).
//   P_neg = F P F^T + Q ; S = H P_neg H^T + R ; K = P_neg H^T S^-1
//   P_pos = P_neg - sym(K W^T) ; A = F - K (H F)
// Gauss-Jordan inverse of S inside warp 0 via shuffles. Stops at convergence
// (max|dP| < 1e-6); consumers clamp t to d_tconv.
// ============================================================================
__global__ void riccati_kernel(const float* __restrict__ Fg,
                               const float* __restrict__ Hg,
                               const float* __restrict__ Qg,
                               const float* __restrict__ Rg)
{
    __shared__ float Fs[100], Hs[100], HFs[100];
    __shared__ float P[100], FP[100], Pn[100], W[100], Ssh[100], Sinv[100], Ks[100];

    const int tid = threadIdx.x;
    const int r = tid / 10, c = tid % 10;
    const bool act = tid < 100;

    if (act) { Fs[tid] = Fg[tid]; Hs[tid] = Hg[tid]; }
    __syncthreads();

    float Frow[10], FrowC[10], HrowR[10], HrowC[10], HFcol[10];
    float qv = 0.f, rv = 0.f;
    if (act) {
        qv = Qg[tid]; rv = Rg[tid];
        #pragma unroll
        for (int j = 0; j < 10; ++j) {
            Frow[j]  = Fs[r*10+j];
            FrowC[j] = Fs[c*10+j];
            HrowR[j] = Hs[r*10+j];
            HrowC[j] = Hs[c*10+j];
        }
        float s = 0.f;
        #pragma unroll
        for (int j = 0; j < 10; ++j) s += HrowR[j] * Fs[j*10+c];
        HFs[tid] = s;
        P[tid] = (r == c) ? 1.f : 0.f;
    }
    __syncthreads();
    if (act) {
        #pragma unroll
        for (int j = 0; j < 10; ++j) HFcol[j] = HFs[j*10+c];
    }

    int tconv = T_STEPS - 1;
    for (int t = 0; t < T_STEPS; ++t) {
        if (act) {
            float s = 0.f;
            #pragma unroll
            for (int j = 0; j < 10; ++j) s += Frow[j] * P[j*10+c];
            FP[tid] = s;
        }
        __syncthreads();
        if (act) {
            float s = qv;
            #pragma unroll
            for (int j = 0; j < 10; ++j) s += FP[r*10+j] * FrowC[j];
            Pn[tid] = s;
        }
        __syncthreads();
        if (act) {
            float s = 0.f;
            #pragma unroll
            for (int j = 0; j < 10; ++j) s += Pn[r*10+j] * HrowC[j];
            W[tid] = s;
        }
        __syncthreads();
        if (act) {
            float s = rv;
            #pragma unroll
            for (int j = 0; j < 10; ++j) s += HrowR[j] * W[j*10+c];
            Ssh[tid] = s;
        }
        __syncthreads();
        if (tid < 32) {
            const int lr = (tid < 10) ? tid : 0;
            float sv[10];
            #pragma unroll
            for (int j = 0; j < 10; ++j) sv[j] = Ssh[lr*10+j];
            #pragma unroll
            for (int k = 0; k < 10; ++k) {
                float rk[10];
                #pragma unroll
                for (int j = 0; j < 10; ++j)
                    rk[j] = __shfl_sync(0xffffffffu, sv[j], k);
                float pinv = 1.0f / rk[k];
                if (tid == k) {
                    #pragma unroll
                    for (int j = 0; j < 10; ++j) sv[j] = rk[j] * pinv;
                    sv[k] = pinv;
                } else {
                    float f = sv[k] * pinv;
                    #pragma unroll
                    for (int j = 0; j < 10; ++j)
                        if (j != k) sv[j] -= f * rk[j];
                    sv[k] = -f;
                }
            }
            if (tid < 10) {
                #pragma unroll
                for (int j = 0; j < 10; ++j) Sinv[tid*10+j] = sv[j];
            }
        }
        __syncthreads();
        if (act) {
            float s = 0.f;
            #pragma unroll
            for (int j = 0; j < 10; ++j) s += W[r*10+j] * Sinv[j*10+c];
            Ks[tid] = s;
        }
        __syncthreads();
        bool pred = false;
        if (act) {
            float s1 = 0.f, s2 = 0.f, sa = 0.f;
            #pragma unroll
            for (int j = 0; j < 10; ++j) {
                s1 += Ks[r*10+j] * W[c*10+j];
                s2 += W[r*10+j] * Ks[c*10+j];
                sa += Ks[r*10+j] * HFcol[j];
            }
            float pnew = Pn[tid] - 0.5f * (s1 + s2);
            float aval = Fs[tid] - sa;
            pred = fabsf(pnew - P[tid]) > 1e-6f;
            d_Pp  [t*100 + tid] = pnew;
            d_Kmat[t*100 + tid] = Ks[tid];
            d_Amat[t*100 + tid] = aval;
            P[tid] = pnew;
        }
        if (!__syncthreads_or(pred)) { tconv = t; break; }
    }
    if (tid == 0) d_tconv = tconv;
}

// ---------------------------------------------------------------------------
// group-of-10 affine step: lane holds x[row]; matvec via shuffles.
//   xn[row] = sum_j K[l][row,j]*y[j] + A[l][row,j]*x[j]
// ---------------------------------------------------------------------------
__device__ __forceinline__ float group_step(const float* __restrict__ Kl,
                                            const float* __restrict__ Al,
                                            float y, float x, int sub, int row)
{
    float sk = 0.f, sa = 0.f;
    #pragma unroll
    for (int j = 0; j < 10; ++j) {
        float yj = __shfl_sync(0xffffffffu, y, sub*10 + j);
        float xj = __shfl_sync(0xffffffffu, x, sub*10 + j);
        sk += Kl[row*10 + j] * yj;
        sa += Al[row*10 + j] * xj;
    }
    return sk + sa;
}

// ============================================================================
// Kernel 2 (fused launch): role-split blocks, interleaved so pk's DRAM stores
// overlap chunkv/chunkmat compute.
//   even b, idx<NB_V : chunkv  (group-of-10 zero-start scan -> d_Vc)
//   even b, idx>=NB_V: chunkmat (M_c products -> d_Mc)
//   odd  b           : pk broadcast writes
// ============================================================================
__global__ void fused_mid_kernel(const float* __restrict__ Y,
                                 float* __restrict__ out, int out_size)
{
    __shared__ float sA[CLEN*100];
    __shared__ float sK[CLEN*100];
    const int b = blockIdx.x;
    const int tid = threadIdx.x;
    const int tconv = d_tconv;

    if (b & 1) {
        // ------------------- pk role -------------------
        const int pkb = b >> 1;
        long tg = (long)pkb * blockDim.x + tid;
        if (tg < NTRAJ*NS && out_size >= OUT_TRAJ_SIZE) {
            int traj = (int)(tg / NS), i = (int)(tg % NS);
            out[(size_t)traj*TRAJ_STRIDE + i] = 0.f;
        }
        if (out_size < OUT_PK_OFF + 4) return;
        long total4 = (long)OUT_PK_SIZE / 4;
        long lim4 = ((long)out_size - OUT_PK_OFF) / 4;
        if (lim4 < total4) total4 = lim4;
        float4* outp = (float4*)(out + OUT_PK_OFF);
        const long stride = (long)NB_PK * blockDim.x;
        for (long idx = tg; idx < total4; idx += stride) {
            int e4 = (int)(idx % 25);
            long rem = idx / 25;
            int t = (int)(rem % (T_STEPS + 1));
            float4 v;
            if (t == 0) v = make_float4(0.f, 0.f, 0.f, 0.f);
            else {
                int tc = min(t - 1, tconv);
                v = *(const float4*)&d_Pp[tc*100 + e4*4];
            }
            outp[idx] = v;
        }
        return;
    }

    const int idx = b >> 1;
    if (idx < NB_V) {
        // ------------------- chunkv role -------------------
        const int chunk = idx / 11;
        const int slice = idx % 11;
        for (int i = tid; i < CLEN*100; i += blockDim.x) {
            int l = i / 100, e = i % 100;
            int tc = min(chunk*CLEN + l, tconv);
            sA[i] = d_Amat[tc*100 + e];
            sK[i] = d_Kmat[tc*100 + e];
        }
        __syncthreads();

        const int warpId = tid / 32, lane = tid % 32;
        const int sub = lane / 10, row = lane - sub*10;
        const int g = slice*24 + warpId*3 + sub;
        const bool valid = (lane < 30) && (g < NTRAJ);
        const int traj = valid ? g : 0;

        float v = 0.f;
        const float* yb = Y + (size_t)traj * (T_STEPS*NS) + chunk*CLEN*NS;
        #pragma unroll
        for (int l = 0; l < CLEN; ++l) {
            float y = yb[l*10 + row];
            v = group_step(&sK[l*100], &sA[l*100], y, v, sub, row);
        }
        if (valid)
            d_Vc[((size_t)chunk*NTRAJ + traj)*NS + row] = v;
    } else {
        // ------------------- chunkmat role -------------------
        const int chunk = idx - NB_V;
        for (int i = tid; i < CLEN*100; i += blockDim.x) {
            int l = i / 100, e = i % 100;
            int tc = min(chunk*CLEN + l, tconv);
            sA[i] = d_Amat[tc*100 + e];
        }
        __syncthreads();
        float* Mb = sK;   // reuse as Mb[2][100]
        const int r = tid / 10, c = tid % 10;
        const bool act = tid < 100;
        if (act) Mb[tid] = sA[tid];
        __syncthreads();
        for (int l = 1; l < CLEN; ++l) {
            if (act) {
                float s = 0.f;
                #pragma unroll
                for (int j = 0; j < 10; ++j)
                    s += sA[l*100 + r*10+j] * Mb[((l-1)&1)*100 + j*10+c];
                Mb[(l&1)*100 + tid] = s;
            }
            __syncthreads();
        }
        if (act) d_Mc[chunk*100 + tid] = Mb[((CLEN-1)&1)*100 + tid];
    }
}

// ============================================================================
// Kernel 3: serial chain over chunks (shuffle-based, barrier-free loop).
// 10 lanes per trajectory (3 traj/warp), all 100 M matrices in smem,
// 4-deep register prefetch pipeline for V. grid=11, block=256.
// ============================================================================
#define CS_STEP(CH, VREG)                                                      \
    do {                                                                       \
        if (valid) d_Xst[((size_t)(CH)*NTRAJ + traj)*NS + row] = x;            \
        float xn = (VREG);                                                     \
        _Pragma("unroll")                                                      \
        for (int j = 0; j < 10; ++j)                                           \
            xn += Ms[(CH)*100 + row*10 + j] *                                  \
                  __shfl_sync(0xffffffffu, x, sub*10 + j);                     \
        x = xn;                                                                \
    } while (0)

__global__ void chainscan_kernel()
{
    __shared__ float Ms[CHUNKS*100];   // 40 KB
    const int tid = threadIdx.x;
    {
        const float4* src = (const float4*)d_Mc;
        float4* dst = (float4*)Ms;
        for (int i = tid; i < CHUNKS*100/4; i += blockDim.x) dst[i] = src[i];
    }
    __syncthreads();

    const int warpId = tid / 32, lane = tid % 32;
    const int sub = lane / 10, row = lane - sub*10;
    const int traj = (blockIdx.x * (blockDim.x/32) + warpId) * 3 + sub;
    const bool valid = (lane < 30) && (traj < NTRAJ);

    float x = 0.f;
    float vb0, vb1, vb2, vb3;
    #define LDV(CH) ((valid && (CH) < CHUNKS) ? d_Vc[((size_t)(CH)*NTRAJ + traj)*NS + row] : 0.f)
    vb0 = LDV(0); vb1 = LDV(1); vb2 = LDV(2); vb3 = LDV(3);
    for (int ch = 0; ch < CHUNKS; ch += 4) {
        CS_STEP(ch + 0, vb0); vb0 = LDV(ch + 4);
        CS_STEP(ch + 1, vb1); vb1 = LDV(ch + 5);
        CS_STEP(ch + 2, vb2); vb2 = LDV(ch + 6);
        CS_STEP(ch + 3, vb3); vb3 = LDV(ch + 7);
    }
    #undef LDV
}

// ============================================================================
// Kernel 4: replay (group-of-10 lanes). grid=(CHUNKS, 11), block=256.
// Writes traj output + per-(chunk,traj) squared-error.
// ============================================================================
__global__ void replay_kernel(const float* __restrict__ Y,
                              const float* __restrict__ X,
                              float* __restrict__ out, int out_size)
{
    __shared__ float sA[CLEN*100];
    __shared__ float sK[CLEN*100];
    const int chunk = blockIdx.x;
    const int slice = blockIdx.y;
    const int tid = threadIdx.x;
    const int tconv = d_tconv;

    for (int i = tid; i < CLEN*100; i += blockDim.x) {
        int l = i / 100, e = i % 100;
        int tc = min(chunk*CLEN + l, tconv);
        sA[i] = d_Amat[tc*100 + e];
        sK[i] = d_Kmat[tc*100 + e];
    }
    __syncthreads();

    const int warpId = tid / 32, lane = tid % 32;
    const int sub = lane / 10, row = lane - sub*10;
    const int g = slice*24 + warpId*3 + sub;
    const bool valid = (lane < 30) && (g < NTRAJ);
    const int traj = valid ? g : 0;

    float x = d_Xst[((size_t)chunk*NTRAJ + traj)*NS + row];

    const bool wr = valid && (out_size >= OUT_TRAJ_SIZE);
    float errsum = 0.f;
    const float* yb = Y + (size_t)traj * (T_STEPS*NS);
    const float* xb = X + (size_t)traj * TRAJ_STRIDE;
    float* ob = out + (size_t)traj * TRAJ_STRIDE;

    #pragma unroll
    for (int l = 0; l < CLEN; ++l) {
        const int t = chunk*CLEN + l;
        float y = yb[t*10 + row];
        x = group_step(&sK[l*100], &sA[l*100], y, x, sub, row);
        if (wr) ob[(t+1)*10 + row] = x;
        float d = xb[(t+1)*10 + row] - x;
        errsum += d * d;
    }

    // gather the 10 lane partials of this group
    float tot = 0.f;
    #pragma unroll
    for (int j = 0; j < 10; ++j)
        tot += __shfl_sync(0xffffffffu, errsum, sub*10 + j);
    if (valid && row == 0)
        d_partial[(size_t)chunk*NTRAJ + traj] = tot;
}

// ============================================================================
// Kernel 5: MSE reduction -> scalar (dB averaged over trajectories)
// ============================================================================
__global__ void mse_kernel(float* __restrict__ out, int out_size)
{
    __shared__ float red[NTRAJ];
    const int traj = threadIdx.x;
    float s = 0.f;
    for (int ch = 0; ch < CHUNKS; ++ch) s += d_partial[(size_t)ch*NTRAJ + traj];
    float mse = s / (float)(T_STEPS * NS);
    red[traj] = 10.f * log10f(mse);
    __syncthreads();
    for (int off = NTRAJ/2; off > 0; off >>= 1) {
        if (traj < off) red[traj] += red[traj + off];
        __syncthreads();
    }
    if (traj == 0 && OUT_MSE_OFF < out_size)
        out[OUT_MSE_OFF] = red[0] / (float)NTRAJ;
}

// ============================================================================
extern "C" void kernel_launch(void* const* d_in, const int* in_sizes, int n_in,
                              void* d_out, int out_size)
{
    const float* X = (const float*)d_in[0];
    const float* Y = (const float*)d_in[1];
    const float* F = (const float*)d_in[2];
    const float* H = (const float*)d_in[3];
    const float* Q = (const float*)d_in[4];
    const float* R = (const float*)d_in[5];
    float* out = (float*)d_out;

    riccati_kernel  <<<1, 128>>>(F, H, Q, R);
    fused_mid_kernel<<<NB_MID, 256>>>(Y, out, out_size);
    chainscan_kernel<<<11, 256>>>();
    replay_kernel   <<<dim3(CHUNKS, 11), 256>>>(Y, X, out, out_size);
    mse_kernel      <<<1, NTRAJ>>>(out, out_size);
}